// round 11
// baseline (speedup 1.0000x reference)
#include <cuda_runtime.h>
#include <cuda_fp16.h>
#include <math.h>
#include <cstdint>

// Problem: B=2, T=2048, C=768, H=12, D=64.  M = B*T = 4096 rows.
#define M_ROWS 4096
#define C_DIM  768
#define T_SEQ  2048
#define H_HEADS 12
#define D_HEAD 64
#define QKV_LD (3*C_DIM)   // 2304
#define FC_DIM (4*C_DIM)   // 3072

// ---------------- scratch (device globals: no allocation allowed) -------------
__device__ __half g_xn [M_ROWS * C_DIM];
__device__ __half g_qkv[M_ROWS * QKV_LD];   // fp16 natural layout
__device__ __half g_y  [M_ROWS * C_DIM];    // attention partial 0 -> merged y
__device__ __half g_y2 [M_ROWS * C_DIM];    // attention partial 1
__device__ float  g_x2 [M_ROWS * C_DIM];
__device__ __half g_h  [M_ROWS * FC_DIM];
// transposed (K-major, fp16, k-permuted) weights
__device__ __half g_wattnT[QKV_LD * C_DIM];
__device__ __half g_wprojT[C_DIM * C_DIM];
__device__ __half g_wfcT  [FC_DIM * C_DIM];
__device__ __half g_wmlpT [C_DIM * FC_DIM];

// ======================= helpers ==============================================
__device__ __forceinline__ uint32_t smem_u32(const void* p) {
    uint32_t a;
    asm("{ .reg .u64 t; cvta.to.shared.u64 t, %1; cvt.u32.u64 %0, t; }" : "=r"(a) : "l"(p));
    return a;
}
__device__ __forceinline__ void cp_async16(uint32_t s, const void* g) {
    asm volatile("cp.async.cg.shared.global [%0], [%1], 16;" :: "r"(s), "l"(g));
}
#define CP_COMMIT() asm volatile("cp.async.commit_group;" ::: "memory")
#define CP_WAIT(n)  asm volatile("cp.async.wait_group %0;" :: "n"(n) : "memory")

__device__ __forceinline__ float exp2a(float x) {
    float r;
    asm("ex2.approx.ftz.f32 %0, %1;" : "=f"(r) : "f"(x));
    return r;
}
// permute k within 16-groups: a thread's mma fragment halves
// {2t4, 2t4+1, 2t4+8, 2t4+9} become 4 contiguous halves at 16g + 4*t4.
__device__ __forceinline__ int perm16(int k) {
    int lo = k & 15;
    int p = ((lo & 7) >> 1) * 4 + ((lo >> 3) << 1) + (lo & 1);
    return (k & ~15) | p;
}
// smem half-index for tile row r, half col k; 16B-unit XOR swizzle
__device__ __forceinline__ int haddr(int r, int k) {
    int u = k >> 3;
    return r * 64 + (((u ^ (r & 7)) << 3) | (k & 7));
}
// D(16x8,f32) += A(16x16,f16) * B(16x8,f16)
__device__ __forceinline__ void mma_f16(float* d, const uint32_t* a, const uint32_t* b) {
    asm volatile(
        "mma.sync.aligned.m16n8k16.row.col.f32.f16.f16.f32 "
        "{%0,%1,%2,%3}, {%4,%5,%6,%7}, {%8,%9}, {%0,%1,%2,%3};"
        : "+f"(d[0]), "+f"(d[1]), "+f"(d[2]), "+f"(d[3])
        : "r"(a[0]), "r"(a[1]), "r"(a[2]), "r"(a[3]), "r"(b[0]), "r"(b[1]));
}
#define LDMX4(r, addr) \
    asm volatile("ldmatrix.sync.aligned.m8n8.x4.shared.b16 {%0,%1,%2,%3}, [%4];" \
        : "=r"((r)[0]), "=r"((r)[1]), "=r"((r)[2]), "=r"((r)[3]) : "r"(addr))
#define LDMX4T(r, addr) \
    asm volatile("ldmatrix.sync.aligned.m8n8.x4.trans.shared.b16 {%0,%1,%2,%3}, [%4];" \
        : "=r"((r)[0]), "=r"((r)[1]), "=r"((r)[2]), "=r"((r)[3]) : "r"(addr))

// ---------------- LayerNorm, warp-per-row (output: fp16, k-permuted) ----------
__global__ __launch_bounds__(256) void ln_kernel(const float* __restrict__ x,
                                                 const float* __restrict__ w,
                                                 __half* __restrict__ out) {
    int row = blockIdx.x * 8 + (threadIdx.x >> 5);
    int lane = threadIdx.x & 31;
    const float* xr = x + (size_t)row * C_DIM;
    float4 v[6];
    float s = 0.f, s2 = 0.f;
    #pragma unroll
    for (int j = 0; j < 6; j++) {
        v[j] = *(const float4*)(xr + j * 128 + lane * 4);
        s  += v[j].x + v[j].y + v[j].z + v[j].w;
        s2 += v[j].x * v[j].x + v[j].y * v[j].y + v[j].z * v[j].z + v[j].w * v[j].w;
    }
    #pragma unroll
    for (int o = 16; o; o >>= 1) {
        s  += __shfl_xor_sync(0xFFFFFFFFu, s,  o);
        s2 += __shfl_xor_sync(0xFFFFFFFFu, s2, o);
    }
    float mean = s * (1.f / C_DIM);
    float var  = s2 * (1.f / C_DIM) - mean * mean;
    float inv  = rsqrtf(var + 1e-5f);
    __half* orow = out + (size_t)row * C_DIM;
    #pragma unroll
    for (int j = 0; j < 6; j++) {
        int c = j * 128 + lane * 4;
        const float* f = &v[j].x;
        #pragma unroll
        for (int q = 0; q < 4; q++)
            orow[perm16(c + q)] = __float2half((f[q] - mean) * inv * w[c + q]);
    }
}

// ---------------- All 4 weight transposes in one launch ------------------------
#define SEG0 1728
#define SEG1 (SEG0 + 576)
#define SEG2 (SEG1 + 2304)
#define SEG3 (SEG2 + 2304)    // 6912 total

__global__ __launch_bounds__(256) void transpose_all_kernel(
    const float* __restrict__ in0, __half* __restrict__ out0,
    const float* __restrict__ in1, __half* __restrict__ out1,
    const float* __restrict__ in2, __half* __restrict__ out2,
    const float* __restrict__ in3, __half* __restrict__ out3)
{
    int bid = blockIdx.x;
    const float* in; __half* out; int rows, cols, t0, ntx;
    if (bid < SEG0)      { in = in0; out = out0; rows = C_DIM;  cols = QKV_LD; t0 = 0;    ntx = QKV_LD / 32; }
    else if (bid < SEG1) { in = in1; out = out1; rows = C_DIM;  cols = C_DIM;  t0 = SEG0; ntx = C_DIM / 32; }
    else if (bid < SEG2) { in = in2; out = out2; rows = C_DIM;  cols = FC_DIM; t0 = SEG1; ntx = FC_DIM / 32; }
    else                 { in = in3; out = out3; rows = FC_DIM; cols = C_DIM;  t0 = SEG2; ntx = C_DIM / 32; }
    int t = bid - t0;
    int bx = (t % ntx) * 32;
    int by = (t / ntx) * 32;

    __shared__ float tile[32][33];
    int tx = threadIdx.x & 31, ty = threadIdx.x >> 5;
    int x = bx + tx;
    #pragma unroll
    for (int j = 0; j < 32; j += 8)
        tile[ty + j][tx] = in[(size_t)(by + ty + j) * cols + x];
    __syncthreads();
    int ox = by + tx;
    #pragma unroll
    for (int j = 0; j < 32; j += 8) {
        float v = tile[tx][ty + j];
        out[(size_t)(bx + ty + j) * rows + perm16(ox)] = __float2half(v);
    }
}

// ---------------- fp16 mma GEMM, 128xTN CTA tile, 3-stage cp.async ------------
// MODE 0: C = A@B -> fp16 natural ; MODE 1: C = A@B + R -> f32 ;
// MODE 2: C = gelu(A@B) -> fp16, k-permuted
// TN=256: warp tile 64x64, 1 CTA/SM. TN=128: warp tile 64x32, 2 CTAs/SM.
template<int MODE, int TN>
__global__ __launch_bounds__(256, (TN == 128) ? 2 : 1) void mma_gemm_kernel(
    const __half* __restrict__ A, const __half* __restrict__ BT,
    const float* __restrict__ R, void* __restrict__ Cv,
    int M, int N, int K)
{
    constexpr int NT = TN / 32;                 // n-tiles per warp (8 or 4)
    constexpr int STG = (128 + TN) * 64;        // halves per stage
    constexpr int BITER = TN / 32;              // B cp.async iters

    extern __shared__ __half smh[];
    uint32_t sm_u = smem_u32(smh);

    int tid  = threadIdx.x;
    int wid  = tid >> 5, lane = tid & 31;
    int wm   = wid & 1;
    int wn   = wid >> 1;
    int g    = lane >> 2, t4 = lane & 3;
    int m0 = blockIdx.y * 128, n0 = blockIdx.x * TN;

    float acc[4][NT][4];
    #pragma unroll
    for (int i = 0; i < 4; i++)
        #pragma unroll
        for (int j = 0; j < NT; j++)
            #pragma unroll
            for (int q = 0; q < 4; q++) acc[i][j][q] = 0.f;

    const int nch = K >> 6;

    auto issue = [&](int k0, int s) {
        uint32_t sb = sm_u + (uint32_t)(s * STG) * 2;
        #pragma unroll
        for (int t = 0; t < 4; t++) {
            int idx = t * 256 + tid;
            int row = idx >> 3, u = idx & 7;
            cp_async16(sb + (uint32_t)(row * 64 + ((u ^ (row & 7)) << 3)) * 2,
                       A + (size_t)(m0 + row) * K + k0 + u * 8);
        }
        uint32_t bb = sb + 8192u * 2;
        #pragma unroll
        for (int t = 0; t < BITER; t++) {
            int idx = t * 256 + tid;
            int row = idx >> 3, u = idx & 7;
            cp_async16(bb + (uint32_t)(row * 64 + ((u ^ (row & 7)) << 3)) * 2,
                       BT + (size_t)(n0 + row) * K + k0 + u * 8);
        }
    };

    issue(0, 0); CP_COMMIT();
    if (nch > 1) { issue(64, 1); CP_COMMIT(); }

    for (int ic = 0; ic < nch; ic++) {
        if (ic + 1 < nch) CP_WAIT(1);
        else              CP_WAIT(0);
        __syncthreads();
        if (ic + 2 < nch) { issue((ic + 2) * 64, (ic + 2) % 3); CP_COMMIT(); }

        const __half* Ah = smh + (ic % 3) * STG;
        const __half* Bh = Ah + 8192;
        #pragma unroll
        for (int ks = 0; ks < 4; ks++) {
            uint32_t a[4][4], b[NT][2];
            int kc = ks * 16 + 4 * t4;
            #pragma unroll
            for (int mt = 0; mt < 4; mt++) {
                int r = wm * 64 + mt * 16 + g;
                uint2 lo = *(const uint2*)(Ah + haddr(r,     kc));
                uint2 hi = *(const uint2*)(Ah + haddr(r + 8, kc));
                a[mt][0] = lo.x; a[mt][2] = lo.y;
                a[mt][1] = hi.x; a[mt][3] = hi.y;
            }
            #pragma unroll
            for (int nt = 0; nt < NT; nt++) {
                int nr = wn * (TN / 4) + nt * 8 + g;
                uint2 bv = *(const uint2*)(Bh + haddr(nr, kc));
                b[nt][0] = bv.x; b[nt][1] = bv.y;
            }
            #pragma unroll
            for (int mt = 0; mt < 4; mt++)
                #pragma unroll
                for (int nt = 0; nt < NT; nt++)
                    mma_f16(acc[mt][nt], a[mt], b[nt]);
        }
    }

    #pragma unroll
    for (int mt = 0; mt < 4; mt++) {
        int r0 = m0 + wm * 64 + mt * 16 + g;
        #pragma unroll
        for (int nt = 0; nt < NT; nt++) {
            int c = n0 + wn * (TN / 4) + nt * 8 + 2 * t4;
            #pragma unroll
            for (int half_ = 0; half_ < 2; half_++) {
                int r = r0 + half_ * 8;
                float v0 = acc[mt][nt][half_ * 2 + 0];
                float v1 = acc[mt][nt][half_ * 2 + 1];
                if (MODE == 1) {
                    float* C = (float*)Cv;
                    float2 rv = *(const float2*)(R + (size_t)r * N + c);
                    v0 += rv.x; v1 += rv.y;
                    *(float2*)(C + (size_t)r * N + c) = make_float2(v0, v1);
                } else if (MODE == 2) {
                    __half* C = (__half*)Cv;
                    v0 = 0.5f * v0 * (1.0f + erff(v0 * 0.70710678118654752f));
                    v1 = 0.5f * v1 * (1.0f + erff(v1 * 0.70710678118654752f));
                    C[(size_t)r * N + perm16(c)]     = __float2half(v0);
                    C[(size_t)r * N + perm16(c + 1)] = __float2half(v1);
                } else {
                    __half* C = (__half*)Cv;
                    *(__half2*)(C + (size_t)r * N + c) = __floats2half2_rn(v0, v1);
                }
            }
        }
    }
}

// ---------------- Attention: fp16 mma, 128q blocks, split-K (2 CTAs/block) ----
// scores = exp(s*(q2+k2-2qk)), s=-1/16; exp(s*k2) folded into V per tile so the
// per-element path is 1 FMA + 1 ex2.approx. Causal, unnormalized, split-K sums.
#define ATTN_SMEM_BYTES (24576 * 2 + 128 * 4)

__global__ __launch_bounds__(256, 2) void attn_kernel(const __half* __restrict__ qkv,
                                                      __half* __restrict__ y0,
                                                      __half* __restrict__ y1) {
    int qi = gridDim.x - 1 - blockIdx.x;   // big blocks first
    int h = blockIdx.y;
    int b = blockIdx.z & 1;
    int sp = blockIdx.z >> 1;              // split index 0/1
    int kt0 = sp * (qi + 1);
    int kt1 = kt0 + qi + 1;
    __half* yb = sp ? y1 : y0;

    extern __shared__ __half smh[];
    __half* Qs = smh;                 // 128 x 64
    __half* Ks = smh + 8192;          // 2 x 64 x 64
    __half* Vs = smh + 16384;         // 2 x 64 x 64
    float* q2s = (float*)(smh + 24576);   // 128
    uint32_t Qu = smem_u32(Qs), Ku = smem_u32(Ks), Vu = smem_u32(Vs);

    int tid = threadIdx.x, wid = tid >> 5, lane = tid & 31;
    int g = lane >> 2, t4 = lane & 3;
    int qrow0 = wid * 16;
    const float scale = -0.0625f;              // -1/(2*sqrt(64))
    const float L2E   = 1.44269504f;
    const float C2L   = 0.125f * L2E;          // (-2*scale)*log2e

    // load Q (128 rows x 8 units)
    {
        const __half* qg = qkv + ((size_t)(b * T_SEQ + qi * 128)) * QKV_LD + h * 64;
        #pragma unroll
        for (int t = 0; t < 4; t++) {
            int idx = t * 256 + tid;
            int r = idx >> 3, u = idx & 7;
            cp_async16(Qu + (uint32_t)(r * 64 + ((u ^ (r & 7)) << 3)) * 2,
                       qg + (size_t)r * QKV_LD + u * 8);
        }
    }
    auto loadKV = [&](int kt, int bb) {
        const __half* kg = qkv + ((size_t)(b * T_SEQ + kt * 64)) * QKV_LD + C_DIM + h * 64;
        const __half* vg = kg + C_DIM;
        uint32_t kb = Ku + (uint32_t)(bb * 4096) * 2;
        uint32_t vb = Vu + (uint32_t)(bb * 4096) * 2;
        #pragma unroll
        for (int t = 0; t < 2; t++) {
            int idx = t * 256 + tid;
            int r = idx >> 3, u = idx & 7;
            uint32_t so = (uint32_t)(r * 64 + ((u ^ (r & 7)) << 3)) * 2;
            cp_async16(kb + so, kg + (size_t)r * QKV_LD + u * 8);
            cp_async16(vb + so, vg + (size_t)r * QKV_LD + u * 8);
        }
    };
    loadKV(kt0, 0); CP_COMMIT();

    uint32_t qf[4][4];
    float oacc[8][4];
    #pragma unroll
    for (int i = 0; i < 8; i++)
        #pragma unroll
        for (int q = 0; q < 4; q++) oacc[i][q] = 0.f;

    int qg0 = qi * 128 + qrow0 + g;
    int qg1 = qg0 + 8;
    float ra2a = 0.f, ra2b = 0.f;   // scale*q2*log2e per row

    for (int kt = kt0; kt < kt1; kt++) {
        int buf = (kt - kt0) & 1;
        if (kt + 1 < kt1) { loadKV(kt + 1, buf ^ 1); CP_COMMIT(); CP_WAIT(1); }
        else              { CP_WAIT(0); }
        __syncthreads();

        if (kt == kt0 && tid < 128) {      // q2 (once per CTA)
            int r = tid;
            float s = 0.f;
            #pragma unroll
            for (int u = 0; u < 8; u++) {
                uint4 v = *(const uint4*)(Qs + r * 64 + ((u ^ (r & 7)) << 3));
                const uint32_t* w = &v.x;
                #pragma unroll
                for (int j = 0; j < 4; j++) {
                    float2 f = __half22float2(*(const __half2*)&w[j]);
                    s += f.x * f.x + f.y * f.y;
                }
            }
            q2s[r] = s;
        }

        // ---- quad pass: k2 per key row, fold exp(scale*k2) into V ----
        {
            int r = tid >> 2;              // key row 0..63
            int seg = tid & 3;             // 16-half segment
            const __half* kb = Ks + buf * 4096;
            __half* vb = Vs + buf * 4096;
            uint4 kv0 = *(const uint4*)(kb + r * 64 + seg * 16);
            uint4 kv1 = *(const uint4*)(kb + r * 64 + seg * 16 + 8);
            float s = 0.f;
            const uint32_t* w0 = &kv0.x;
            const uint32_t* w1 = &kv1.x;
            #pragma unroll
            for (int j = 0; j < 4; j++) {
                float2 f0 = __half22float2(*(const __half2*)&w0[j]);
                float2 f1 = __half22float2(*(const __half2*)&w1[j]);
                s += f0.x * f0.x + f0.y * f0.y + f1.x * f1.x + f1.y * f1.y;
            }
            s += __shfl_xor_sync(0xFFFFFFFFu, s, 1);
            s += __shfl_xor_sync(0xFFFFFFFFu, s, 2);
            float ek = exp2a(scale * L2E * s);
            __half2 ekh = __float2half2_rn(ek);
            uint4 vv0 = *(const uint4*)(vb + r * 64 + seg * 16);
            uint4 vv1 = *(const uint4*)(vb + r * 64 + seg * 16 + 8);
            __half2* h0 = (__half2*)&vv0;
            __half2* h1 = (__half2*)&vv1;
            #pragma unroll
            for (int j = 0; j < 4; j++) { h0[j] = __hmul2(h0[j], ekh); h1[j] = __hmul2(h1[j], ekh); }
            *(uint4*)(vb + r * 64 + seg * 16)     = vv0;
            *(uint4*)(vb + r * 64 + seg * 16 + 8) = vv1;
        }
        __syncthreads();

        if (kt == kt0) {
            #pragma unroll
            for (int ks = 0; ks < 4; ks++) {
                int m = lane >> 3;
                int r = qrow0 + ((m & 1) << 3) + (lane & 7);
                int d0 = ks * 16 + ((m >> 1) << 3);
                LDMX4(qf[ks], Qu + (uint32_t)haddr(r, d0) * 2);
            }
            ra2a = scale * L2E * q2s[qrow0 + g];
            ra2b = scale * L2E * q2s[qrow0 + g + 8];
        }

        uint32_t kbase = Ku + (uint32_t)(buf * 4096) * 2;
        uint32_t vbase = Vu + (uint32_t)(buf * 4096) * 2;

        // ---- S = Q @ K^T ----
        float sacc[8][4];
        #pragma unroll
        for (int i = 0; i < 8; i++)
            #pragma unroll
            for (int q = 0; q < 4; q++) sacc[i][q] = 0.f;
        #pragma unroll
        for (int ks = 0; ks < 4; ks++) {
            uint32_t kf[4][4];
            #pragma unroll
            for (int nt2 = 0; nt2 < 4; nt2++) {
                int m = lane >> 3;
                int tok = nt2 * 16 + ((m >> 1) << 3) + (lane & 7);
                int d0 = ks * 16 + ((m & 1) << 3);
                LDMX4(kf[nt2], kbase + (uint32_t)haddr(tok, d0) * 2);
            }
            #pragma unroll
            for (int nt2 = 0; nt2 < 4; nt2++) {
                mma_f16(sacc[2 * nt2],     qf[ks], &kf[nt2][0]);
                mma_f16(sacc[2 * nt2 + 1], qf[ks], &kf[nt2][2]);
            }
        }

        // ---- P' = exp2(fma(qk, C2L, ra2)), causal mask, fp16 in registers ----
        uint32_t ph[8], ph2[8];
        int kc0 = kt * 64 + 2 * t4;
        #pragma unroll
        for (int nt = 0; nt < 8; nt++) {
            int c0 = kc0 + nt * 8;
            float e00 = (c0     <= qg0) ? exp2a(fmaf(sacc[nt][0], C2L, ra2a)) : 0.f;
            float e01 = (c0 + 1 <= qg0) ? exp2a(fmaf(sacc[nt][1], C2L, ra2a)) : 0.f;
            float e10 = (c0     <= qg1) ? exp2a(fmaf(sacc[nt][2], C2L, ra2b)) : 0.f;
            float e11 = (c0 + 1 <= qg1) ? exp2a(fmaf(sacc[nt][3], C2L, ra2b)) : 0.f;
            __half2 p0 = __floats2half2_rn(e00, e01);
            __half2 p1 = __floats2half2_rn(e10, e11);
            ph[nt]  = *(uint32_t*)&p0;
            ph2[nt] = *(uint32_t*)&p1;
        }

        // ---- O += P' @ V' ----
        #pragma unroll
        for (int kc = 0; kc < 4; kc++) {
            uint32_t vf[4][4];
            #pragma unroll
            for (int dn2 = 0; dn2 < 4; dn2++) {
                int m = lane >> 3;
                int tok = kc * 16 + ((m & 1) << 3) + (lane & 7);
                int d0 = dn2 * 16 + ((m >> 1) << 3);
                LDMX4T(vf[dn2], vbase + (uint32_t)haddr(tok, d0) * 2);
            }
            uint32_t a[4] = { ph[2 * kc], ph2[2 * kc], ph[2 * kc + 1], ph2[2 * kc + 1] };
            #pragma unroll
            for (int dn2 = 0; dn2 < 4; dn2++) {
                mma_f16(oacc[2 * dn2],     a, &vf[dn2][0]);
                mma_f16(oacc[2 * dn2 + 1], a, &vf[dn2][2]);
            }
        }
        __syncthreads();
    }

    // ---- write partial y (fp16, perm16) ----
    size_t row0 = (size_t)(b * T_SEQ + qi * 128 + qrow0 + g);
    #pragma unroll
    for (int dn = 0; dn < 8; dn++) {
        int col = h * 64 + dn * 8 + 2 * t4;
        int pc = perm16(col);
        __half2 v0 = __floats2half2_rn(oacc[dn][0], oacc[dn][1]);
        __half2 v1 = __floats2half2_rn(oacc[dn][2], oacc[dn][3]);
        *(__half2*)(yb + row0 * C_DIM + pc)       = v0;
        *(__half2*)(yb + (row0 + 8) * C_DIM + pc) = v1;
    }
}

// ---------------- merge split-K partials: y = y0 + y1 (in place on y0) --------
__global__ __launch_bounds__(256) void merge_y_kernel(__half2* __restrict__ y0,
                                                      const __half2* __restrict__ y1) {
    const int n2 = M_ROWS * C_DIM / 2;
    int i = blockIdx.x * 256 + threadIdx.x;
    int stride = gridDim.x * 256;
    for (; i < n2; i += stride)
        y0[i] = __hadd2(y0[i], y1[i]);
}

// ---------------- launch ------------------------------------------------------
extern "C" void kernel_launch(void* const* d_in, const int* in_sizes, int n_in,
                              void* d_out, int out_size) {
    const float* x           = (const float*)d_in[0];
    const float* w_ln1       = (const float*)d_in[1];
    const float* w_attn      = (const float*)d_in[2];
    const float* w_attn_proj = (const float*)d_in[3];
    const float* w_ln2       = (const float*)d_in[4];
    const float* w_fc        = (const float*)d_in[5];
    const float* w_mlp_proj  = (const float*)d_in[6];
    float* out = (float*)d_out;

    __half *xn, *qkv, *y, *y2, *hbuf, *wattnT, *wprojT, *wfcT, *wmlpT;
    float *x2;
    cudaGetSymbolAddress((void**)&xn,     g_xn);
    cudaGetSymbolAddress((void**)&qkv,    g_qkv);
    cudaGetSymbolAddress((void**)&y,      g_y);
    cudaGetSymbolAddress((void**)&y2,     g_y2);
    cudaGetSymbolAddress((void**)&x2,     g_x2);
    cudaGetSymbolAddress((void**)&hbuf,   g_h);
    cudaGetSymbolAddress((void**)&wattnT, g_wattnT);
    cudaGetSymbolAddress((void**)&wprojT, g_wprojT);
    cudaGetSymbolAddress((void**)&wfcT,   g_wfcT);
    cudaGetSymbolAddress((void**)&wmlpT,  g_wmlpT);

    const int SM256 = 3 * (128 + 256) * 64 * 2;   // 147456
    const int SM128 = 3 * (128 + 128) * 64 * 2;   // 98304
    cudaFuncSetAttribute(attn_kernel, cudaFuncAttributeMaxDynamicSharedMemorySize, ATTN_SMEM_BYTES);
    cudaFuncSetAttribute(mma_gemm_kernel<0, 256>, cudaFuncAttributeMaxDynamicSharedMemorySize, SM256);
    cudaFuncSetAttribute(mma_gemm_kernel<2, 256>, cudaFuncAttributeMaxDynamicSharedMemorySize, SM256);
    cudaFuncSetAttribute(mma_gemm_kernel<1, 128>, cudaFuncAttributeMaxDynamicSharedMemorySize, SM128);

    // 0. all weight transposes, one launch
    transpose_all_kernel<<<SEG3, 256>>>(w_attn, wattnT, w_attn_proj, wprojT,
                                        w_fc, wfcT, w_mlp_proj, wmlpT);
    // 1. ln1(x) -> xn  (fp16, k-permuted)
    ln_kernel<<<M_ROWS / 8, 256>>>(x, w_ln1, xn);
    // 2. qkv = xn @ w_attn  (fp16 natural out)
    mma_gemm_kernel<0, 256><<<dim3(QKV_LD / 256, M_ROWS / 128), 256, SM256>>>(
        xn, wattnT, nullptr, qkv, M_ROWS, QKV_LD, C_DIM);
    // 3. attention, 2-way split-K -> y (partial 0), y2 (partial 1)
    attn_kernel<<<dim3(T_SEQ / 128, H_HEADS, 4), 256, ATTN_SMEM_BYTES>>>(qkv, y, y2);
    // 3b. y += y2
    merge_y_kernel<<<1184, 256>>>((__half2*)y, (const __half2*)y2);
    // 4. x2 = y @ w_attn_proj + x  (f32 out; 128-wide tiles -> 192 CTAs)
    mma_gemm_kernel<1, 128><<<dim3(C_DIM / 128, M_ROWS / 128), 256, SM128>>>(
        y, wprojT, x, x2, M_ROWS, C_DIM, C_DIM);
    // 5. ln2(x2) -> xn
    ln_kernel<<<M_ROWS / 8, 256>>>(x2, w_ln2, xn);
    // 6. h = gelu(xn @ w_fc)  (fp16, k-permuted)
    mma_gemm_kernel<2, 256><<<dim3(FC_DIM / 256, M_ROWS / 128), 256, SM256>>>(
        xn, wfcT, nullptr, hbuf, M_ROWS, FC_DIM, C_DIM);
    // 7. out = h @ w_mlp_proj + x2  (f32 out; 128-wide tiles -> 192 CTAs)
    mma_gemm_kernel<1, 128><<<dim3(C_DIM / 128, M_ROWS / 128), 256, SM128>>>(
        hbuf, wmlpT, x2, out, M_ROWS, C_DIM, FC_DIM);
}

// round 12
// speedup vs baseline: 1.3596x; 1.3596x over previous
#include <cuda_runtime.h>
#include <cuda_fp16.h>
#include <math.h>
#include <cstdint>

// Problem: B=2, T=2048, C=768, H=12, D=64.  M = B*T = 4096 rows.
#define M_ROWS 4096
#define C_DIM  768
#define T_SEQ  2048
#define H_HEADS 12
#define D_HEAD 64
#define QKV_LD (3*C_DIM)   // 2304
#define FC_DIM (4*C_DIM)   // 3072

// ---------------- scratch (device globals: no allocation allowed) -------------
__device__ __half g_xn [M_ROWS * C_DIM];
__device__ __half g_qkv[M_ROWS * QKV_LD];   // fp16 natural layout
__device__ __half g_y  [M_ROWS * C_DIM];    // attention partial 0 -> merged y
__device__ __half g_y2 [M_ROWS * C_DIM];    // attention partial 1
__device__ float  g_x2 [M_ROWS * C_DIM];
__device__ __half g_h  [M_ROWS * FC_DIM];
// transposed (K-major, fp16, natural k-order) weights
__device__ __half g_wattnT[QKV_LD * C_DIM];
__device__ __half g_wprojT[C_DIM * C_DIM];
__device__ __half g_wfcT  [FC_DIM * C_DIM];
__device__ __half g_wmlpT [C_DIM * FC_DIM];

// ======================= helpers ==============================================
__device__ __forceinline__ uint32_t smem_u32(const void* p) {
    uint32_t a;
    asm("{ .reg .u64 t; cvta.to.shared.u64 t, %1; cvt.u32.u64 %0, t; }" : "=r"(a) : "l"(p));
    return a;
}
__device__ __forceinline__ void cp_async16(uint32_t s, const void* g) {
    asm volatile("cp.async.cg.shared.global [%0], [%1], 16;" :: "r"(s), "l"(g));
}
#define CP_COMMIT() asm volatile("cp.async.commit_group;" ::: "memory")
#define CP_WAIT(n)  asm volatile("cp.async.wait_group %0;" :: "n"(n) : "memory")

__device__ __forceinline__ float exp2a(float x) {
    float r;
    asm("ex2.approx.ftz.f32 %0, %1;" : "=f"(r) : "f"(x));
    return r;
}
// smem half-index for tile row r, half col k; 16B-unit XOR swizzle
__device__ __forceinline__ int haddr(int r, int k) {
    int u = k >> 3;
    return r * 64 + (((u ^ (r & 7)) << 3) | (k & 7));
}
// D(16x8,f32) += A(16x16,f16) * B(16x8,f16)
__device__ __forceinline__ void mma_f16(float* d, const uint32_t* a, const uint32_t* b) {
    asm volatile(
        "mma.sync.aligned.m16n8k16.row.col.f32.f16.f16.f32 "
        "{%0,%1,%2,%3}, {%4,%5,%6,%7}, {%8,%9}, {%0,%1,%2,%3};"
        : "+f"(d[0]), "+f"(d[1]), "+f"(d[2]), "+f"(d[3])
        : "r"(a[0]), "r"(a[1]), "r"(a[2]), "r"(a[3]), "r"(b[0]), "r"(b[1]));
}
#define LDMX4(r, addr) \
    asm volatile("ldmatrix.sync.aligned.m8n8.x4.shared.b16 {%0,%1,%2,%3}, [%4];" \
        : "=r"((r)[0]), "=r"((r)[1]), "=r"((r)[2]), "=r"((r)[3]) : "r"(addr))
#define LDMX4T(r, addr) \
    asm volatile("ldmatrix.sync.aligned.m8n8.x4.trans.shared.b16 {%0,%1,%2,%3}, [%4];" \
        : "=r"((r)[0]), "=r"((r)[1]), "=r"((r)[2]), "=r"((r)[3]) : "r"(addr))

// ---------------- LayerNorm, warp-per-row (output: fp16 natural) --------------
__global__ __launch_bounds__(256) void ln_kernel(const float* __restrict__ x,
                                                 const float* __restrict__ w,
                                                 __half* __restrict__ out) {
    int row = blockIdx.x * 8 + (threadIdx.x >> 5);
    int lane = threadIdx.x & 31;
    const float* xr = x + (size_t)row * C_DIM;
    float4 v[6];
    float s = 0.f, s2 = 0.f;
    #pragma unroll
    for (int j = 0; j < 6; j++) {
        v[j] = *(const float4*)(xr + j * 128 + lane * 4);
        s  += v[j].x + v[j].y + v[j].z + v[j].w;
        s2 += v[j].x * v[j].x + v[j].y * v[j].y + v[j].z * v[j].z + v[j].w * v[j].w;
    }
    #pragma unroll
    for (int o = 16; o; o >>= 1) {
        s  += __shfl_xor_sync(0xFFFFFFFFu, s,  o);
        s2 += __shfl_xor_sync(0xFFFFFFFFu, s2, o);
    }
    float mean = s * (1.f / C_DIM);
    float var  = s2 * (1.f / C_DIM) - mean * mean;
    float inv  = rsqrtf(var + 1e-5f);
    __half* orow = out + (size_t)row * C_DIM;
    #pragma unroll
    for (int j = 0; j < 6; j++) {
        int c = j * 128 + lane * 4;
        const float* f = &v[j].x;
        __half2 p0 = __floats2half2_rn((f[0] - mean) * inv * w[c],
                                       (f[1] - mean) * inv * w[c + 1]);
        __half2 p1 = __floats2half2_rn((f[2] - mean) * inv * w[c + 2],
                                       (f[3] - mean) * inv * w[c + 3]);
        *(__half2*)(orow + c)     = p0;
        *(__half2*)(orow + c + 2) = p1;
    }
}

// ---------------- All 4 weight transposes in one launch ------------------------
#define SEG0 1728
#define SEG1 (SEG0 + 576)
#define SEG2 (SEG1 + 2304)
#define SEG3 (SEG2 + 2304)    // 6912 total

__global__ __launch_bounds__(256) void transpose_all_kernel(
    const float* __restrict__ in0, __half* __restrict__ out0,
    const float* __restrict__ in1, __half* __restrict__ out1,
    const float* __restrict__ in2, __half* __restrict__ out2,
    const float* __restrict__ in3, __half* __restrict__ out3)
{
    int bid = blockIdx.x;
    const float* in; __half* out; int rows, cols, t0, ntx;
    if (bid < SEG0)      { in = in0; out = out0; rows = C_DIM;  cols = QKV_LD; t0 = 0;    ntx = QKV_LD / 32; }
    else if (bid < SEG1) { in = in1; out = out1; rows = C_DIM;  cols = C_DIM;  t0 = SEG0; ntx = C_DIM / 32; }
    else if (bid < SEG2) { in = in2; out = out2; rows = C_DIM;  cols = FC_DIM; t0 = SEG1; ntx = FC_DIM / 32; }
    else                 { in = in3; out = out3; rows = FC_DIM; cols = C_DIM;  t0 = SEG2; ntx = C_DIM / 32; }
    int t = bid - t0;
    int bx = (t % ntx) * 32;
    int by = (t / ntx) * 32;

    __shared__ float tile[32][33];
    int tx = threadIdx.x & 31, ty = threadIdx.x >> 5;
    int x = bx + tx;
    #pragma unroll
    for (int j = 0; j < 32; j += 8)
        tile[ty + j][tx] = in[(size_t)(by + ty + j) * cols + x];
    __syncthreads();
    int ox = by + tx;
    #pragma unroll
    for (int j = 0; j < 32; j += 8) {
        float v = tile[tx][ty + j];
        out[(size_t)(bx + ty + j) * rows + ox] = __float2half(v);
    }
}

// ---------------- fp16 mma GEMM, 128x256 CTA tile, ldmatrix mainloop ----------
// MODE 0: C = A@B -> fp16 natural ; MODE 1: C = A@B + R -> f32 ;
// MODE 2: C = gelu(A@B) -> fp16 natural
#define STAGE_H 24576                        // (128 + 256) * 64 halves
#define GEMM_SMEM_BYTES (3 * STAGE_H * 2)    // 147456

template<int MODE>
__global__ __launch_bounds__(256, 1) void mma_gemm_kernel(
    const __half* __restrict__ A, const __half* __restrict__ BT,
    const float* __restrict__ R, void* __restrict__ Cv,
    int M, int N, int K)
{
    extern __shared__ __half smh[];
    uint32_t sm_u = smem_u32(smh);

    int tid  = threadIdx.x;
    int wid  = tid >> 5, lane = tid & 31;
    int wm   = wid & 1;
    int wn   = wid >> 1;
    int g    = lane >> 2, t4 = lane & 3;
    int m0 = blockIdx.y * 128, n0 = blockIdx.x * 256;

    // ldmatrix addressing (same pattern as attention kernel)
    int lm   = lane >> 3;                  // matrix index 0..3
    int arow = ((lm & 1) << 3) + (lane & 7);
    int acol = (lm >> 1) << 3;
    int brow = ((lm >> 1) << 3) + (lane & 7);
    int bcol = (lm & 1) << 3;

    float acc[4][8][4];
    #pragma unroll
    for (int i = 0; i < 4; i++)
        #pragma unroll
        for (int j = 0; j < 8; j++)
            #pragma unroll
            for (int q = 0; q < 4; q++) acc[i][j][q] = 0.f;

    const int nch = K >> 6;

    auto issue = [&](int k0, int s) {
        uint32_t sb = sm_u + (uint32_t)(s * STAGE_H) * 2;
        #pragma unroll
        for (int t = 0; t < 4; t++) {
            int idx = t * 256 + tid;
            int row = idx >> 3, u = idx & 7;
            cp_async16(sb + (uint32_t)(row * 64 + ((u ^ (row & 7)) << 3)) * 2,
                       A + (size_t)(m0 + row) * K + k0 + u * 8);
        }
        uint32_t bb = sb + 8192u * 2;
        #pragma unroll
        for (int t = 0; t < 8; t++) {
            int idx = t * 256 + tid;
            int row = idx >> 3, u = idx & 7;
            cp_async16(bb + (uint32_t)(row * 64 + ((u ^ (row & 7)) << 3)) * 2,
                       BT + (size_t)(n0 + row) * K + k0 + u * 8);
        }
    };

    issue(0, 0); CP_COMMIT();
    if (nch > 1) { issue(64, 1); CP_COMMIT(); }

    for (int ic = 0; ic < nch; ic++) {
        if (ic + 1 < nch) CP_WAIT(1);
        else              CP_WAIT(0);
        __syncthreads();
        if (ic + 2 < nch) { issue((ic + 2) * 64, (ic + 2) % 3); CP_COMMIT(); }

        uint32_t Au = sm_u + (uint32_t)((ic % 3) * STAGE_H) * 2;
        uint32_t Bu = Au + 8192u * 2;
        #pragma unroll
        for (int ks = 0; ks < 4; ks++) {
            uint32_t a[4][4], b[4][4];
            #pragma unroll
            for (int mt = 0; mt < 4; mt++)
                LDMX4(a[mt], Au + (uint32_t)haddr(wm * 64 + mt * 16 + arow,
                                                  ks * 16 + acol) * 2);
            #pragma unroll
            for (int np = 0; np < 4; np++)
                LDMX4(b[np], Bu + (uint32_t)haddr(wn * 64 + np * 16 + brow,
                                                  ks * 16 + bcol) * 2);
            #pragma unroll
            for (int mt = 0; mt < 4; mt++)
                #pragma unroll
                for (int np = 0; np < 4; np++) {
                    mma_f16(acc[mt][2 * np],     a[mt], &b[np][0]);
                    mma_f16(acc[mt][2 * np + 1], a[mt], &b[np][2]);
                }
        }
    }

    #pragma unroll
    for (int mt = 0; mt < 4; mt++) {
        int r0 = m0 + wm * 64 + mt * 16 + g;
        #pragma unroll
        for (int nt = 0; nt < 8; nt++) {
            int c = n0 + wn * 64 + nt * 8 + 2 * t4;
            #pragma unroll
            for (int half_ = 0; half_ < 2; half_++) {
                int r = r0 + half_ * 8;
                float v0 = acc[mt][nt][half_ * 2 + 0];
                float v1 = acc[mt][nt][half_ * 2 + 1];
                if (MODE == 1) {
                    float* C = (float*)Cv;
                    float2 rv = *(const float2*)(R + (size_t)r * N + c);
                    v0 += rv.x; v1 += rv.y;
                    *(float2*)(C + (size_t)r * N + c) = make_float2(v0, v1);
                } else if (MODE == 2) {
                    __half* C = (__half*)Cv;
                    v0 = 0.5f * v0 * (1.0f + erff(v0 * 0.70710678118654752f));
                    v1 = 0.5f * v1 * (1.0f + erff(v1 * 0.70710678118654752f));
                    *(__half2*)(C + (size_t)r * N + c) = __floats2half2_rn(v0, v1);
                } else {
                    __half* C = (__half*)Cv;
                    *(__half2*)(C + (size_t)r * N + c) = __floats2half2_rn(v0, v1);
                }
            }
        }
    }
}

// ---------------- Attention: fp16 mma, 128q blocks, split-K (2 CTAs/block) ----
// scores = exp(s*(q2+k2-2qk)), s=-1/16; exp(s*k2) folded into V per tile so the
// per-element path is 1 FMA + 1 ex2.approx. Causal, unnormalized, split-K sums.
#define ATTN_SMEM_BYTES (24576 * 2 + 128 * 4)

__global__ __launch_bounds__(256, 2) void attn_kernel(const __half* __restrict__ qkv,
                                                      __half* __restrict__ y0,
                                                      __half* __restrict__ y1) {
    int qi = gridDim.x - 1 - blockIdx.x;   // big blocks first
    int h = blockIdx.y;
    int b = blockIdx.z & 1;
    int sp = blockIdx.z >> 1;              // split index 0/1
    int kt0 = sp * (qi + 1);
    int kt1 = kt0 + qi + 1;
    __half* yb = sp ? y1 : y0;

    extern __shared__ __half smh[];
    __half* Qs = smh;                 // 128 x 64
    __half* Ks = smh + 8192;          // 2 x 64 x 64
    __half* Vs = smh + 16384;         // 2 x 64 x 64
    float* q2s = (float*)(smh + 24576);   // 128
    uint32_t Qu = smem_u32(Qs), Ku = smem_u32(Ks), Vu = smem_u32(Vs);

    int tid = threadIdx.x, wid = tid >> 5, lane = tid & 31;
    int g = lane >> 2, t4 = lane & 3;
    int qrow0 = wid * 16;
    const float scale = -0.0625f;              // -1/(2*sqrt(64))
    const float L2E   = 1.44269504f;
    const float C2L   = 0.125f * L2E;          // (-2*scale)*log2e

    // load Q (128 rows x 8 units)
    {
        const __half* qg = qkv + ((size_t)(b * T_SEQ + qi * 128)) * QKV_LD + h * 64;
        #pragma unroll
        for (int t = 0; t < 4; t++) {
            int idx = t * 256 + tid;
            int r = idx >> 3, u = idx & 7;
            cp_async16(Qu + (uint32_t)(r * 64 + ((u ^ (r & 7)) << 3)) * 2,
                       qg + (size_t)r * QKV_LD + u * 8);
        }
    }
    auto loadKV = [&](int kt, int bb) {
        const __half* kg = qkv + ((size_t)(b * T_SEQ + kt * 64)) * QKV_LD + C_DIM + h * 64;
        const __half* vg = kg + C_DIM;
        uint32_t kb = Ku + (uint32_t)(bb * 4096) * 2;
        uint32_t vb = Vu + (uint32_t)(bb * 4096) * 2;
        #pragma unroll
        for (int t = 0; t < 2; t++) {
            int idx = t * 256 + tid;
            int r = idx >> 3, u = idx & 7;
            uint32_t so = (uint32_t)(r * 64 + ((u ^ (r & 7)) << 3)) * 2;
            cp_async16(kb + so, kg + (size_t)r * QKV_LD + u * 8);
            cp_async16(vb + so, vg + (size_t)r * QKV_LD + u * 8);
        }
    };
    loadKV(kt0, 0); CP_COMMIT();

    uint32_t qf[4][4];
    float oacc[8][4];
    #pragma unroll
    for (int i = 0; i < 8; i++)
        #pragma unroll
        for (int q = 0; q < 4; q++) oacc[i][q] = 0.f;

    int qg0 = qi * 128 + qrow0 + g;
    int qg1 = qg0 + 8;
    float ra2a = 0.f, ra2b = 0.f;   // scale*q2*log2e per row

    for (int kt = kt0; kt < kt1; kt++) {
        int buf = (kt - kt0) & 1;
        if (kt + 1 < kt1) { loadKV(kt + 1, buf ^ 1); CP_COMMIT(); CP_WAIT(1); }
        else              { CP_WAIT(0); }
        __syncthreads();

        if (kt == kt0 && tid < 128) {      // q2 (once per CTA)
            int r = tid;
            float s = 0.f;
            #pragma unroll
            for (int u = 0; u < 8; u++) {
                uint4 v = *(const uint4*)(Qs + r * 64 + ((u ^ (r & 7)) << 3));
                const uint32_t* w = &v.x;
                #pragma unroll
                for (int j = 0; j < 4; j++) {
                    float2 f = __half22float2(*(const __half2*)&w[j]);
                    s += f.x * f.x + f.y * f.y;
                }
            }
            q2s[r] = s;
        }

        // ---- quad pass: k2 per key row, fold exp(scale*k2) into V ----
        {
            int r = tid >> 2;              // key row 0..63
            int seg = tid & 3;             // 16-half segment
            const __half* kb = Ks + buf * 4096;
            __half* vb = Vs + buf * 4096;
            uint4 kv0 = *(const uint4*)(kb + r * 64 + seg * 16);
            uint4 kv1 = *(const uint4*)(kb + r * 64 + seg * 16 + 8);
            float s = 0.f;
            const uint32_t* w0 = &kv0.x;
            const uint32_t* w1 = &kv1.x;
            #pragma unroll
            for (int j = 0; j < 4; j++) {
                float2 f0 = __half22float2(*(const __half2*)&w0[j]);
                float2 f1 = __half22float2(*(const __half2*)&w1[j]);
                s += f0.x * f0.x + f0.y * f0.y + f1.x * f1.x + f1.y * f1.y;
            }
            s += __shfl_xor_sync(0xFFFFFFFFu, s, 1);
            s += __shfl_xor_sync(0xFFFFFFFFu, s, 2);
            float ek = exp2a(scale * L2E * s);
            __half2 ekh = __float2half2_rn(ek);
            uint4 vv0 = *(const uint4*)(vb + r * 64 + seg * 16);
            uint4 vv1 = *(const uint4*)(vb + r * 64 + seg * 16 + 8);
            __half2* h0 = (__half2*)&vv0;
            __half2* h1 = (__half2*)&vv1;
            #pragma unroll
            for (int j = 0; j < 4; j++) { h0[j] = __hmul2(h0[j], ekh); h1[j] = __hmul2(h1[j], ekh); }
            *(uint4*)(vb + r * 64 + seg * 16)     = vv0;
            *(uint4*)(vb + r * 64 + seg * 16 + 8) = vv1;
        }
        __syncthreads();

        if (kt == kt0) {
            #pragma unroll
            for (int ks = 0; ks < 4; ks++) {
                int m = lane >> 3;
                int r = qrow0 + ((m & 1) << 3) + (lane & 7);
                int d0 = ks * 16 + ((m >> 1) << 3);
                LDMX4(qf[ks], Qu + (uint32_t)haddr(r, d0) * 2);
            }
            ra2a = scale * L2E * q2s[qrow0 + g];
            ra2b = scale * L2E * q2s[qrow0 + g + 8];
        }

        uint32_t kbase = Ku + (uint32_t)(buf * 4096) * 2;
        uint32_t vbase = Vu + (uint32_t)(buf * 4096) * 2;

        // ---- S = Q @ K^T ----
        float sacc[8][4];
        #pragma unroll
        for (int i = 0; i < 8; i++)
            #pragma unroll
            for (int q = 0; q < 4; q++) sacc[i][q] = 0.f;
        #pragma unroll
        for (int ks = 0; ks < 4; ks++) {
            uint32_t kf[4][4];
            #pragma unroll
            for (int nt2 = 0; nt2 < 4; nt2++) {
                int m = lane >> 3;
                int tok = nt2 * 16 + ((m >> 1) << 3) + (lane & 7);
                int d0 = ks * 16 + ((m & 1) << 3);
                LDMX4(kf[nt2], kbase + (uint32_t)haddr(tok, d0) * 2);
            }
            #pragma unroll
            for (int nt2 = 0; nt2 < 4; nt2++) {
                mma_f16(sacc[2 * nt2],     qf[ks], &kf[nt2][0]);
                mma_f16(sacc[2 * nt2 + 1], qf[ks], &kf[nt2][2]);
            }
        }

        // ---- P' = exp2(fma(qk, C2L, ra2)), causal mask, fp16 in registers ----
        uint32_t ph[8], ph2[8];
        int kc0 = kt * 64 + 2 * t4;
        #pragma unroll
        for (int nt = 0; nt < 8; nt++) {
            int c0 = kc0 + nt * 8;
            float e00 = (c0     <= qg0) ? exp2a(fmaf(sacc[nt][0], C2L, ra2a)) : 0.f;
            float e01 = (c0 + 1 <= qg0) ? exp2a(fmaf(sacc[nt][1], C2L, ra2a)) : 0.f;
            float e10 = (c0     <= qg1) ? exp2a(fmaf(sacc[nt][2], C2L, ra2b)) : 0.f;
            float e11 = (c0 + 1 <= qg1) ? exp2a(fmaf(sacc[nt][3], C2L, ra2b)) : 0.f;
            __half2 p0 = __floats2half2_rn(e00, e01);
            __half2 p1 = __floats2half2_rn(e10, e11);
            ph[nt]  = *(uint32_t*)&p0;
            ph2[nt] = *(uint32_t*)&p1;
        }

        // ---- O += P' @ V' ----
        #pragma unroll
        for (int kc = 0; kc < 4; kc++) {
            uint32_t vf[4][4];
            #pragma unroll
            for (int dn2 = 0; dn2 < 4; dn2++) {
                int m = lane >> 3;
                int tok = kc * 16 + ((m & 1) << 3) + (lane & 7);
                int d0 = dn2 * 16 + ((m >> 1) << 3);
                LDMX4T(vf[dn2], vbase + (uint32_t)haddr(tok, d0) * 2);
            }
            uint32_t a[4] = { ph[2 * kc], ph2[2 * kc], ph[2 * kc + 1], ph2[2 * kc + 1] };
            #pragma unroll
            for (int dn2 = 0; dn2 < 4; dn2++) {
                mma_f16(oacc[2 * dn2],     a, &vf[dn2][0]);
                mma_f16(oacc[2 * dn2 + 1], a, &vf[dn2][2]);
            }
        }
        __syncthreads();
    }

    // ---- write partial y (fp16, natural) ----
    size_t row0 = (size_t)(b * T_SEQ + qi * 128 + qrow0 + g);
    #pragma unroll
    for (int dn = 0; dn < 8; dn++) {
        int col = h * 64 + dn * 8 + 2 * t4;
        __half2 v0 = __floats2half2_rn(oacc[dn][0], oacc[dn][1]);
        __half2 v1 = __floats2half2_rn(oacc[dn][2], oacc[dn][3]);
        *(__half2*)(yb + row0 * C_DIM + col)       = v0;
        *(__half2*)(yb + (row0 + 8) * C_DIM + col) = v1;
    }
}

// ---------------- merge split-K partials: y = y0 + y1 (in place on y0) --------
__global__ __launch_bounds__(256) void merge_y_kernel(__half2* __restrict__ y0,
                                                      const __half2* __restrict__ y1) {
    const int n2 = M_ROWS * C_DIM / 2;
    int i = blockIdx.x * 256 + threadIdx.x;
    int stride = gridDim.x * 256;
    for (; i < n2; i += stride)
        y0[i] = __hadd2(y0[i], y1[i]);
}

// ---------------- launch ------------------------------------------------------
extern "C" void kernel_launch(void* const* d_in, const int* in_sizes, int n_in,
                              void* d_out, int out_size) {
    const float* x           = (const float*)d_in[0];
    const float* w_ln1       = (const float*)d_in[1];
    const float* w_attn      = (const float*)d_in[2];
    const float* w_attn_proj = (const float*)d_in[3];
    const float* w_ln2       = (const float*)d_in[4];
    const float* w_fc        = (const float*)d_in[5];
    const float* w_mlp_proj  = (const float*)d_in[6];
    float* out = (float*)d_out;

    __half *xn, *qkv, *y, *y2, *hbuf, *wattnT, *wprojT, *wfcT, *wmlpT;
    float *x2;
    cudaGetSymbolAddress((void**)&xn,     g_xn);
    cudaGetSymbolAddress((void**)&qkv,    g_qkv);
    cudaGetSymbolAddress((void**)&y,      g_y);
    cudaGetSymbolAddress((void**)&y2,     g_y2);
    cudaGetSymbolAddress((void**)&x2,     g_x2);
    cudaGetSymbolAddress((void**)&hbuf,   g_h);
    cudaGetSymbolAddress((void**)&wattnT, g_wattnT);
    cudaGetSymbolAddress((void**)&wprojT, g_wprojT);
    cudaGetSymbolAddress((void**)&wfcT,   g_wfcT);
    cudaGetSymbolAddress((void**)&wmlpT,  g_wmlpT);

    cudaFuncSetAttribute(attn_kernel, cudaFuncAttributeMaxDynamicSharedMemorySize, ATTN_SMEM_BYTES);
    cudaFuncSetAttribute(mma_gemm_kernel<0>, cudaFuncAttributeMaxDynamicSharedMemorySize, GEMM_SMEM_BYTES);
    cudaFuncSetAttribute(mma_gemm_kernel<1>, cudaFuncAttributeMaxDynamicSharedMemorySize, GEMM_SMEM_BYTES);
    cudaFuncSetAttribute(mma_gemm_kernel<2>, cudaFuncAttributeMaxDynamicSharedMemorySize, GEMM_SMEM_BYTES);

    // 0. all weight transposes, one launch
    transpose_all_kernel<<<SEG3, 256>>>(w_attn, wattnT, w_attn_proj, wprojT,
                                        w_fc, wfcT, w_mlp_proj, wmlpT);
    // 1. ln1(x) -> xn  (fp16 natural)
    ln_kernel<<<M_ROWS / 8, 256>>>(x, w_ln1, xn);
    // 2. qkv = xn @ w_attn  (fp16 natural out)
    mma_gemm_kernel<0><<<dim3(QKV_LD / 256, M_ROWS / 128), 256, GEMM_SMEM_BYTES>>>(
        xn, wattnT, nullptr, qkv, M_ROWS, QKV_LD, C_DIM);
    // 3. attention, 2-way split-K -> y (partial 0), y2 (partial 1)
    attn_kernel<<<dim3(T_SEQ / 128, H_HEADS, 4), 256, ATTN_SMEM_BYTES>>>(qkv, y, y2);
    // 3b. y += y2
    merge_y_kernel<<<1184, 256>>>((__half2*)y, (const __half2*)y2);
    // 4. x2 = y @ w_attn_proj + x  (f32 out)
    mma_gemm_kernel<1><<<dim3(C_DIM / 256, M_ROWS / 128), 256, GEMM_SMEM_BYTES>>>(
        y, wprojT, x, x2, M_ROWS, C_DIM, C_DIM);
    // 5. ln2(x2) -> xn
    ln_kernel<<<M_ROWS / 8, 256>>>(x2, w_ln2, xn);
    // 6. h = gelu(xn @ w_fc)  (fp16 natural)
    mma_gemm_kernel<2><<<dim3(FC_DIM / 256, M_ROWS / 128), 256, GEMM_SMEM_BYTES>>>(
        xn, wfcT, nullptr, hbuf, M_ROWS, FC_DIM, C_DIM);
    // 7. out = h @ w_mlp_proj + x2  (f32 out)
    mma_gemm_kernel<1><<<dim3(C_DIM / 256, M_ROWS / 128), 256, GEMM_SMEM_BYTES>>>(
        hbuf, wmlpT, x2, out, M_ROWS, C_DIM, FC_DIM);
}

// round 13
// speedup vs baseline: 1.3660x; 1.0047x over previous
#include <cuda_runtime.h>
#include <cuda_fp16.h>
#include <math.h>
#include <cstdint>

// Problem: B=2, T=2048, C=768, H=12, D=64.  M = B*T = 4096 rows.
#define M_ROWS 4096
#define C_DIM  768
#define T_SEQ  2048
#define H_HEADS 12
#define D_HEAD 64
#define QKV_LD (3*C_DIM)   // 2304
#define FC_DIM (4*C_DIM)   // 3072

// ---------------- scratch (device globals: no allocation allowed) -------------
__device__ __half g_xn [M_ROWS * C_DIM];
__device__ __half g_qkv[M_ROWS * QKV_LD];   // fp16 natural layout
__device__ __half g_y  [M_ROWS * C_DIM];    // attention partial 0 -> merged y
__device__ __half g_y2 [M_ROWS * C_DIM];    // attention partial 1
__device__ float  g_x2 [M_ROWS * C_DIM];
__device__ __half g_h  [M_ROWS * FC_DIM];
// transposed (K-major, fp16, natural k-order) weights
__device__ __half g_wattnT[QKV_LD * C_DIM];
__device__ __half g_wprojT[C_DIM * C_DIM];
__device__ __half g_wfcT  [FC_DIM * C_DIM];
__device__ __half g_wmlpT [C_DIM * FC_DIM];

// ======================= helpers ==============================================
__device__ __forceinline__ uint32_t smem_u32(const void* p) {
    uint32_t a;
    asm("{ .reg .u64 t; cvta.to.shared.u64 t, %1; cvt.u32.u64 %0, t; }" : "=r"(a) : "l"(p));
    return a;
}
__device__ __forceinline__ void cp_async16(uint32_t s, const void* g) {
    asm volatile("cp.async.cg.shared.global [%0], [%1], 16;" :: "r"(s), "l"(g));
}
#define CP_COMMIT() asm volatile("cp.async.commit_group;" ::: "memory")
#define CP_WAIT(n)  asm volatile("cp.async.wait_group %0;" :: "n"(n) : "memory")

__device__ __forceinline__ float exp2a(float x) {
    float r;
    asm("ex2.approx.ftz.f32 %0, %1;" : "=f"(r) : "f"(x));
    return r;
}
// smem half-index for tile row r, half col k; 16B-unit XOR swizzle
__device__ __forceinline__ int haddr(int r, int k) {
    int u = k >> 3;
    return r * 64 + (((u ^ (r & 7)) << 3) | (k & 7));
}
// D(16x8,f32) += A(16x16,f16) * B(16x8,f16)
__device__ __forceinline__ void mma_f16(float* d, const uint32_t* a, const uint32_t* b) {
    asm volatile(
        "mma.sync.aligned.m16n8k16.row.col.f32.f16.f16.f32 "
        "{%0,%1,%2,%3}, {%4,%5,%6,%7}, {%8,%9}, {%0,%1,%2,%3};"
        : "+f"(d[0]), "+f"(d[1]), "+f"(d[2]), "+f"(d[3])
        : "r"(a[0]), "r"(a[1]), "r"(a[2]), "r"(a[3]), "r"(b[0]), "r"(b[1]));
}
#define LDMX4(r, addr) \
    asm volatile("ldmatrix.sync.aligned.m8n8.x4.shared.b16 {%0,%1,%2,%3}, [%4];" \
        : "=r"((r)[0]), "=r"((r)[1]), "=r"((r)[2]), "=r"((r)[3]) : "r"(addr))
#define LDMX4T(r, addr) \
    asm volatile("ldmatrix.sync.aligned.m8n8.x4.trans.shared.b16 {%0,%1,%2,%3}, [%4];" \
        : "=r"((r)[0]), "=r"((r)[1]), "=r"((r)[2]), "=r"((r)[3]) : "r"(addr))

// ---------------- LayerNorm, warp-per-row (output: fp16 natural) --------------
__global__ __launch_bounds__(256) void ln_kernel(const float* __restrict__ x,
                                                 const float* __restrict__ w,
                                                 __half* __restrict__ out) {
    int row = blockIdx.x * 8 + (threadIdx.x >> 5);
    int lane = threadIdx.x & 31;
    const float* xr = x + (size_t)row * C_DIM;
    float4 v[6];
    float s = 0.f, s2 = 0.f;
    #pragma unroll
    for (int j = 0; j < 6; j++) {
        v[j] = *(const float4*)(xr + j * 128 + lane * 4);
        s  += v[j].x + v[j].y + v[j].z + v[j].w;
        s2 += v[j].x * v[j].x + v[j].y * v[j].y + v[j].z * v[j].z + v[j].w * v[j].w;
    }
    #pragma unroll
    for (int o = 16; o; o >>= 1) {
        s  += __shfl_xor_sync(0xFFFFFFFFu, s,  o);
        s2 += __shfl_xor_sync(0xFFFFFFFFu, s2, o);
    }
    float mean = s * (1.f / C_DIM);
    float var  = s2 * (1.f / C_DIM) - mean * mean;
    float inv  = rsqrtf(var + 1e-5f);
    __half* orow = out + (size_t)row * C_DIM;
    #pragma unroll
    for (int j = 0; j < 6; j++) {
        int c = j * 128 + lane * 4;
        const float* f = &v[j].x;
        __half2 p0 = __floats2half2_rn((f[0] - mean) * inv * w[c],
                                       (f[1] - mean) * inv * w[c + 1]);
        __half2 p1 = __floats2half2_rn((f[2] - mean) * inv * w[c + 2],
                                       (f[3] - mean) * inv * w[c + 3]);
        *(__half2*)(orow + c)     = p0;
        *(__half2*)(orow + c + 2) = p1;
    }
}

// ---------------- All 4 weight transposes in one launch ------------------------
#define SEG0 1728
#define SEG1 (SEG0 + 576)
#define SEG2 (SEG1 + 2304)
#define SEG3 (SEG2 + 2304)    // 6912 total

__global__ __launch_bounds__(256) void transpose_all_kernel(
    const float* __restrict__ in0, __half* __restrict__ out0,
    const float* __restrict__ in1, __half* __restrict__ out1,
    const float* __restrict__ in2, __half* __restrict__ out2,
    const float* __restrict__ in3, __half* __restrict__ out3)
{
    int bid = blockIdx.x;
    const float* in; __half* out; int rows, cols, t0, ntx;
    if (bid < SEG0)      { in = in0; out = out0; rows = C_DIM;  cols = QKV_LD; t0 = 0;    ntx = QKV_LD / 32; }
    else if (bid < SEG1) { in = in1; out = out1; rows = C_DIM;  cols = C_DIM;  t0 = SEG0; ntx = C_DIM / 32; }
    else if (bid < SEG2) { in = in2; out = out2; rows = C_DIM;  cols = FC_DIM; t0 = SEG1; ntx = FC_DIM / 32; }
    else                 { in = in3; out = out3; rows = FC_DIM; cols = C_DIM;  t0 = SEG2; ntx = C_DIM / 32; }
    int t = bid - t0;
    int bx = (t % ntx) * 32;
    int by = (t / ntx) * 32;

    __shared__ float tile[32][33];
    int tx = threadIdx.x & 31, ty = threadIdx.x >> 5;
    int x = bx + tx;
    #pragma unroll
    for (int j = 0; j < 32; j += 8)
        tile[ty + j][tx] = in[(size_t)(by + ty + j) * cols + x];
    __syncthreads();
    int ox = by + tx;
    #pragma unroll
    for (int j = 0; j < 32; j += 8) {
        float v = tile[tx][ty + j];
        out[(size_t)(bx + ty + j) * rows + ox] = __float2half(v);
    }
}

// ---------------- fp16 mma GEMM, 128x256 CTA tile, ldmatrix mainloop ----------
// MODE 0: C = A@B -> fp16 natural ; MODE 1: C = A@B + R -> f32 ;
// MODE 2: C = gelu(A@B) -> fp16 natural
#define STAGE_H 24576                        // (128 + 256) * 64 halves
#define GEMM_SMEM_BYTES (3 * STAGE_H * 2)    // 147456

template<int MODE>
__global__ __launch_bounds__(256, 1) void mma_gemm_kernel(
    const __half* __restrict__ A, const __half* __restrict__ BT,
    const float* __restrict__ R, void* __restrict__ Cv,
    int M, int N, int K)
{
    extern __shared__ __half smh[];
    uint32_t sm_u = smem_u32(smh);

    int tid  = threadIdx.x;
    int wid  = tid >> 5, lane = tid & 31;
    int wm   = wid & 1;
    int wn   = wid >> 1;
    int g    = lane >> 2, t4 = lane & 3;
    int m0 = blockIdx.y * 128, n0 = blockIdx.x * 256;

    // ldmatrix addressing (same pattern as attention kernel)
    int lm   = lane >> 3;                  // matrix index 0..3
    int arow = ((lm & 1) << 3) + (lane & 7);
    int acol = (lm >> 1) << 3;
    int brow = ((lm >> 1) << 3) + (lane & 7);
    int bcol = (lm & 1) << 3;

    float acc[4][8][4];
    #pragma unroll
    for (int i = 0; i < 4; i++)
        #pragma unroll
        for (int j = 0; j < 8; j++)
            #pragma unroll
            for (int q = 0; q < 4; q++) acc[i][j][q] = 0.f;

    const int nch = K >> 6;

    auto issue = [&](int k0, int s) {
        uint32_t sb = sm_u + (uint32_t)(s * STAGE_H) * 2;
        #pragma unroll
        for (int t = 0; t < 4; t++) {
            int idx = t * 256 + tid;
            int row = idx >> 3, u = idx & 7;
            cp_async16(sb + (uint32_t)(row * 64 + ((u ^ (row & 7)) << 3)) * 2,
                       A + (size_t)(m0 + row) * K + k0 + u * 8);
        }
        uint32_t bb = sb + 8192u * 2;
        #pragma unroll
        for (int t = 0; t < 8; t++) {
            int idx = t * 256 + tid;
            int row = idx >> 3, u = idx & 7;
            cp_async16(bb + (uint32_t)(row * 64 + ((u ^ (row & 7)) << 3)) * 2,
                       BT + (size_t)(n0 + row) * K + k0 + u * 8);
        }
    };

    issue(0, 0); CP_COMMIT();
    if (nch > 1) { issue(64, 1); CP_COMMIT(); }

    for (int ic = 0; ic < nch; ic++) {
        if (ic + 1 < nch) CP_WAIT(1);
        else              CP_WAIT(0);
        __syncthreads();
        if (ic + 2 < nch) { issue((ic + 2) * 64, (ic + 2) % 3); CP_COMMIT(); }

        uint32_t Au = sm_u + (uint32_t)((ic % 3) * STAGE_H) * 2;
        uint32_t Bu = Au + 8192u * 2;
        #pragma unroll
        for (int ks = 0; ks < 4; ks++) {
            uint32_t a[4][4], b[4][4];
            #pragma unroll
            for (int mt = 0; mt < 4; mt++)
                LDMX4(a[mt], Au + (uint32_t)haddr(wm * 64 + mt * 16 + arow,
                                                  ks * 16 + acol) * 2);
            #pragma unroll
            for (int np = 0; np < 4; np++)
                LDMX4(b[np], Bu + (uint32_t)haddr(wn * 64 + np * 16 + brow,
                                                  ks * 16 + bcol) * 2);
            #pragma unroll
            for (int mt = 0; mt < 4; mt++)
                #pragma unroll
                for (int np = 0; np < 4; np++) {
                    mma_f16(acc[mt][2 * np],     a[mt], &b[np][0]);
                    mma_f16(acc[mt][2 * np + 1], a[mt], &b[np][2]);
                }
        }
    }

    #pragma unroll
    for (int mt = 0; mt < 4; mt++) {
        int r0 = m0 + wm * 64 + mt * 16 + g;
        #pragma unroll
        for (int nt = 0; nt < 8; nt++) {
            int c = n0 + wn * 64 + nt * 8 + 2 * t4;
            #pragma unroll
            for (int half_ = 0; half_ < 2; half_++) {
                int r = r0 + half_ * 8;
                float v0 = acc[mt][nt][half_ * 2 + 0];
                float v1 = acc[mt][nt][half_ * 2 + 1];
                if (MODE == 1) {
                    float* C = (float*)Cv;
                    float2 rv = *(const float2*)(R + (size_t)r * N + c);
                    v0 += rv.x; v1 += rv.y;
                    *(float2*)(C + (size_t)r * N + c) = make_float2(v0, v1);
                } else if (MODE == 2) {
                    __half* C = (__half*)Cv;
                    v0 = 0.5f * v0 * (1.0f + erff(v0 * 0.70710678118654752f));
                    v1 = 0.5f * v1 * (1.0f + erff(v1 * 0.70710678118654752f));
                    *(__half2*)(C + (size_t)r * N + c) = __floats2half2_rn(v0, v1);
                } else {
                    __half* C = (__half*)Cv;
                    *(__half2*)(C + (size_t)r * N + c) = __floats2half2_rn(v0, v1);
                }
            }
        }
    }
}

// ---------------- Attention: fp16 mma, 128q blocks, split-K (2 CTAs/block) ----
// scores = exp(s*(q2+k2-2qk)), s=-1/16; exp(s*k2) folded into V per tile so the
// per-element path is 1 FMA + 1 ex2.approx. Causal, unnormalized, split-K sums.
#define ATTN_SMEM_BYTES (24576 * 2 + 128 * 4)

__global__ __launch_bounds__(256, 2) void attn_kernel(const __half* __restrict__ qkv,
                                                      __half* __restrict__ y0,
                                                      __half* __restrict__ y1) {
    int qi = gridDim.x - 1 - blockIdx.x;   // big blocks first
    int h = blockIdx.y;
    int b = blockIdx.z & 1;
    int sp = blockIdx.z >> 1;              // split index 0/1
    int kt0 = sp * (qi + 1);
    int kt1 = kt0 + qi + 1;
    __half* yb = sp ? y1 : y0;

    extern __shared__ __half smh[];
    __half* Qs = smh;                 // 128 x 64
    __half* Ks = smh + 8192;          // 2 x 64 x 64
    __half* Vs = smh + 16384;         // 2 x 64 x 64
    float* q2s = (float*)(smh + 24576);   // 128
    uint32_t Qu = smem_u32(Qs), Ku = smem_u32(Ks), Vu = smem_u32(Vs);

    int tid = threadIdx.x, wid = tid >> 5, lane = tid & 31;
    int g = lane >> 2, t4 = lane & 3;
    int qrow0 = wid * 16;
    const float scale = -0.0625f;              // -1/(2*sqrt(64))
    const float L2E   = 1.44269504f;
    const float C2L   = 0.125f * L2E;          // (-2*scale)*log2e

    // load Q (128 rows x 8 units)
    {
        const __half* qg = qkv + ((size_t)(b * T_SEQ + qi * 128)) * QKV_LD + h * 64;
        #pragma unroll
        for (int t = 0; t < 4; t++) {
            int idx = t * 256 + tid;
            int r = idx >> 3, u = idx & 7;
            cp_async16(Qu + (uint32_t)(r * 64 + ((u ^ (r & 7)) << 3)) * 2,
                       qg + (size_t)r * QKV_LD + u * 8);
        }
    }
    auto loadKV = [&](int kt, int bb) {
        const __half* kg = qkv + ((size_t)(b * T_SEQ + kt * 64)) * QKV_LD + C_DIM + h * 64;
        const __half* vg = kg + C_DIM;
        uint32_t kb = Ku + (uint32_t)(bb * 4096) * 2;
        uint32_t vb = Vu + (uint32_t)(bb * 4096) * 2;
        #pragma unroll
        for (int t = 0; t < 2; t++) {
            int idx = t * 256 + tid;
            int r = idx >> 3, u = idx & 7;
            uint32_t so = (uint32_t)(r * 64 + ((u ^ (r & 7)) << 3)) * 2;
            cp_async16(kb + so, kg + (size_t)r * QKV_LD + u * 8);
            cp_async16(vb + so, vg + (size_t)r * QKV_LD + u * 8);
        }
    };
    loadKV(kt0, 0); CP_COMMIT();

    uint32_t qf[4][4];
    float oacc[8][4];
    #pragma unroll
    for (int i = 0; i < 8; i++)
        #pragma unroll
        for (int q = 0; q < 4; q++) oacc[i][q] = 0.f;

    int qg0 = qi * 128 + qrow0 + g;
    int qg1 = qg0 + 8;
    float ra2a = 0.f, ra2b = 0.f;   // scale*q2*log2e per row

    for (int kt = kt0; kt < kt1; kt++) {
        int buf = (kt - kt0) & 1;
        if (kt + 1 < kt1) { loadKV(kt + 1, buf ^ 1); CP_COMMIT(); CP_WAIT(1); }
        else              { CP_WAIT(0); }
        __syncthreads();

        if (kt == kt0 && tid < 128) {      // q2 (once per CTA)
            int r = tid;
            float s = 0.f;
            #pragma unroll
            for (int u = 0; u < 8; u++) {
                uint4 v = *(const uint4*)(Qs + r * 64 + ((u ^ (r & 7)) << 3));
                const uint32_t* w = &v.x;
                #pragma unroll
                for (int j = 0; j < 4; j++) {
                    float2 f = __half22float2(*(const __half2*)&w[j]);
                    s += f.x * f.x + f.y * f.y;
                }
            }
            q2s[r] = s;
        }

        // ---- quad pass: k2 per key row, fold exp(scale*k2) into V ----
        {
            int r = tid >> 2;              // key row 0..63
            int seg = tid & 3;             // 16-half segment
            const __half* kb = Ks + buf * 4096;
            __half* vb = Vs + buf * 4096;
            uint4 kv0 = *(const uint4*)(kb + r * 64 + seg * 16);
            uint4 kv1 = *(const uint4*)(kb + r * 64 + seg * 16 + 8);
            float s = 0.f;
            const uint32_t* w0 = &kv0.x;
            const uint32_t* w1 = &kv1.x;
            #pragma unroll
            for (int j = 0; j < 4; j++) {
                float2 f0 = __half22float2(*(const __half2*)&w0[j]);
                float2 f1 = __half22float2(*(const __half2*)&w1[j]);
                s += f0.x * f0.x + f0.y * f0.y + f1.x * f1.x + f1.y * f1.y;
            }
            s += __shfl_xor_sync(0xFFFFFFFFu, s, 1);
            s += __shfl_xor_sync(0xFFFFFFFFu, s, 2);
            float ek = exp2a(scale * L2E * s);
            __half2 ekh = __float2half2_rn(ek);
            uint4 vv0 = *(const uint4*)(vb + r * 64 + seg * 16);
            uint4 vv1 = *(const uint4*)(vb + r * 64 + seg * 16 + 8);
            __half2* h0 = (__half2*)&vv0;
            __half2* h1 = (__half2*)&vv1;
            #pragma unroll
            for (int j = 0; j < 4; j++) { h0[j] = __hmul2(h0[j], ekh); h1[j] = __hmul2(h1[j], ekh); }
            *(uint4*)(vb + r * 64 + seg * 16)     = vv0;
            *(uint4*)(vb + r * 64 + seg * 16 + 8) = vv1;
        }
        __syncthreads();

        if (kt == kt0) {
            #pragma unroll
            for (int ks = 0; ks < 4; ks++) {
                int m = lane >> 3;
                int r = qrow0 + ((m & 1) << 3) + (lane & 7);
                int d0 = ks * 16 + ((m >> 1) << 3);
                LDMX4(qf[ks], Qu + (uint32_t)haddr(r, d0) * 2);
            }
            ra2a = scale * L2E * q2s[qrow0 + g];
            ra2b = scale * L2E * q2s[qrow0 + g + 8];
        }

        uint32_t kbase = Ku + (uint32_t)(buf * 4096) * 2;
        uint32_t vbase = Vu + (uint32_t)(buf * 4096) * 2;

        // ---- S = Q @ K^T ----
        float sacc[8][4];
        #pragma unroll
        for (int i = 0; i < 8; i++)
            #pragma unroll
            for (int q = 0; q < 4; q++) sacc[i][q] = 0.f;
        #pragma unroll
        for (int ks = 0; ks < 4; ks++) {
            uint32_t kf[4][4];
            #pragma unroll
            for (int nt2 = 0; nt2 < 4; nt2++) {
                int m = lane >> 3;
                int tok = nt2 * 16 + ((m >> 1) << 3) + (lane & 7);
                int d0 = ks * 16 + ((m & 1) << 3);
                LDMX4(kf[nt2], kbase + (uint32_t)haddr(tok, d0) * 2);
            }
            #pragma unroll
            for (int nt2 = 0; nt2 < 4; nt2++) {
                mma_f16(sacc[2 * nt2],     qf[ks], &kf[nt2][0]);
                mma_f16(sacc[2 * nt2 + 1], qf[ks], &kf[nt2][2]);
            }
        }

        // ---- P' = exp2(fma(qk, C2L, ra2)), causal mask, fp16 in registers ----
        uint32_t ph[8], ph2[8];
        int kc0 = kt * 64 + 2 * t4;
        #pragma unroll
        for (int nt = 0; nt < 8; nt++) {
            int c0 = kc0 + nt * 8;
            float e00 = (c0     <= qg0) ? exp2a(fmaf(sacc[nt][0], C2L, ra2a)) : 0.f;
            float e01 = (c0 + 1 <= qg0) ? exp2a(fmaf(sacc[nt][1], C2L, ra2a)) : 0.f;
            float e10 = (c0     <= qg1) ? exp2a(fmaf(sacc[nt][2], C2L, ra2b)) : 0.f;
            float e11 = (c0 + 1 <= qg1) ? exp2a(fmaf(sacc[nt][3], C2L, ra2b)) : 0.f;
            __half2 p0 = __floats2half2_rn(e00, e01);
            __half2 p1 = __floats2half2_rn(e10, e11);
            ph[nt]  = *(uint32_t*)&p0;
            ph2[nt] = *(uint32_t*)&p1;
        }

        // ---- O += P' @ V' ----
        #pragma unroll
        for (int kc = 0; kc < 4; kc++) {
            uint32_t vf[4][4];
            #pragma unroll
            for (int dn2 = 0; dn2 < 4; dn2++) {
                int m = lane >> 3;
                int tok = kc * 16 + ((m & 1) << 3) + (lane & 7);
                int d0 = dn2 * 16 + ((m >> 1) << 3);
                LDMX4T(vf[dn2], vbase + (uint32_t)haddr(tok, d0) * 2);
            }
            uint32_t a[4] = { ph[2 * kc], ph2[2 * kc], ph[2 * kc + 1], ph2[2 * kc + 1] };
            #pragma unroll
            for (int dn2 = 0; dn2 < 4; dn2++) {
                mma_f16(oacc[2 * dn2],     a, &vf[dn2][0]);
                mma_f16(oacc[2 * dn2 + 1], a, &vf[dn2][2]);
            }
        }
        __syncthreads();
    }

    // ---- write partial y (fp16, natural) ----
    size_t row0 = (size_t)(b * T_SEQ + qi * 128 + qrow0 + g);
    #pragma unroll
    for (int dn = 0; dn < 8; dn++) {
        int col = h * 64 + dn * 8 + 2 * t4;
        __half2 v0 = __floats2half2_rn(oacc[dn][0], oacc[dn][1]);
        __half2 v1 = __floats2half2_rn(oacc[dn][2], oacc[dn][3]);
        *(__half2*)(yb + row0 * C_DIM + col)       = v0;
        *(__half2*)(yb + (row0 + 8) * C_DIM + col) = v1;
    }
}

// ---------------- merge split-K partials: y = y0 + y1 (in place on y0) --------
__global__ __launch_bounds__(256) void merge_y_kernel(__half2* __restrict__ y0,
                                                      const __half2* __restrict__ y1) {
    const int n2 = M_ROWS * C_DIM / 2;
    int i = blockIdx.x * 256 + threadIdx.x;
    int stride = gridDim.x * 256;
    for (; i < n2; i += stride)
        y0[i] = __hadd2(y0[i], y1[i]);
}

// ---------------- launch ------------------------------------------------------
extern "C" void kernel_launch(void* const* d_in, const int* in_sizes, int n_in,
                              void* d_out, int out_size) {
    const float* x           = (const float*)d_in[0];
    const float* w_ln1       = (const float*)d_in[1];
    const float* w_attn      = (const float*)d_in[2];
    const float* w_attn_proj = (const float*)d_in[3];
    const float* w_ln2       = (const float*)d_in[4];
    const float* w_fc        = (const float*)d_in[5];
    const float* w_mlp_proj  = (const float*)d_in[6];
    float* out = (float*)d_out;

    __half *xn, *qkv, *y, *y2, *hbuf, *wattnT, *wprojT, *wfcT, *wmlpT;
    float *x2;
    cudaGetSymbolAddress((void**)&xn,     g_xn);
    cudaGetSymbolAddress((void**)&qkv,    g_qkv);
    cudaGetSymbolAddress((void**)&y,      g_y);
    cudaGetSymbolAddress((void**)&y2,     g_y2);
    cudaGetSymbolAddress((void**)&x2,     g_x2);
    cudaGetSymbolAddress((void**)&hbuf,   g_h);
    cudaGetSymbolAddress((void**)&wattnT, g_wattnT);
    cudaGetSymbolAddress((void**)&wprojT, g_wprojT);
    cudaGetSymbolAddress((void**)&wfcT,   g_wfcT);
    cudaGetSymbolAddress((void**)&wmlpT,  g_wmlpT);

    cudaFuncSetAttribute(attn_kernel, cudaFuncAttributeMaxDynamicSharedMemorySize, ATTN_SMEM_BYTES);
    cudaFuncSetAttribute(mma_gemm_kernel<0>, cudaFuncAttributeMaxDynamicSharedMemorySize, GEMM_SMEM_BYTES);
    cudaFuncSetAttribute(mma_gemm_kernel<1>, cudaFuncAttributeMaxDynamicSharedMemorySize, GEMM_SMEM_BYTES);
    cudaFuncSetAttribute(mma_gemm_kernel<2>, cudaFuncAttributeMaxDynamicSharedMemorySize, GEMM_SMEM_BYTES);

    // 0. all weight transposes, one launch
    transpose_all_kernel<<<SEG3, 256>>>(w_attn, wattnT, w_attn_proj, wprojT,
                                        w_fc, wfcT, w_mlp_proj, wmlpT);
    // 1. ln1(x) -> xn  (fp16 natural)
    ln_kernel<<<M_ROWS / 8, 256>>>(x, w_ln1, xn);
    // 2. qkv = xn @ w_attn  (fp16 natural out)
    mma_gemm_kernel<0><<<dim3(QKV_LD / 256, M_ROWS / 128), 256, GEMM_SMEM_BYTES>>>(
        xn, wattnT, nullptr, qkv, M_ROWS, QKV_LD, C_DIM);
    // 3. attention, 2-way split-K -> y (partial 0), y2 (partial 1)
    attn_kernel<<<dim3(T_SEQ / 128, H_HEADS, 4), 256, ATTN_SMEM_BYTES>>>(qkv, y, y2);
    // 3b. y += y2
    merge_y_kernel<<<1184, 256>>>((__half2*)y, (const __half2*)y2);
    // 4. x2 = y @ w_attn_proj + x  (f32 out)
    mma_gemm_kernel<1><<<dim3(C_DIM / 256, M_ROWS / 128), 256, GEMM_SMEM_BYTES>>>(
        y, wprojT, x, x2, M_ROWS, C_DIM, C_DIM);
    // 5. ln2(x2) -> xn
    ln_kernel<<<M_ROWS / 8, 256>>>(x2, w_ln2, xn);
    // 6. h = gelu(xn @ w_fc)  (fp16 natural)
    mma_gemm_kernel<2><<<dim3(FC_DIM / 256, M_ROWS / 128), 256, GEMM_SMEM_BYTES>>>(
        xn, wfcT, nullptr, hbuf, M_ROWS, FC_DIM, C_DIM);
    // 7. out = h @ w_mlp_proj + x2  (f32 out)
    mma_gemm_kernel<1><<<dim3(C_DIM / 256, M_ROWS / 128), 256, GEMM_SMEM_BYTES>>>(
        hbuf, wmlpT, x2, out, M_ROWS, C_DIM, FC_DIM);
}